// round 2
// baseline (speedup 1.0000x reference)
#include <cuda_runtime.h>

#define NC 10000
#define NK 4
#define ND 2048
#define NP (NC * NK)            // 40000 prototypes
#define WARPS_PER_BLOCK 8
#define BLOCK_THREADS (WARPS_PER_BLOCK * 32)
#define GRID_BLOCKS ((NP + WARPS_PER_BLOCK - 1) / WARPS_PER_BLOCK)  // 5000

// Scratch: squared distances for all prototypes (160 KB, L2-resident for pass 2)
__device__ float g_d[NP];

// ---------------------------------------------------------------------------
// Kernel 1: one warp per prototype row. Stream the 8 KB row as float4,
// accumulate (p - f)^2, warp-reduce, write g_d[row].
// ---------------------------------------------------------------------------
__global__ __launch_bounds__(BLOCK_THREADS)
void dist_kernel(const float* __restrict__ proto, const float* __restrict__ feat) {
    __shared__ float4 sf4[ND / 4];

    const int tid = threadIdx.x;
    const float4* __restrict__ f4 = reinterpret_cast<const float4*>(feat);
    for (int i = tid; i < ND / 4; i += BLOCK_THREADS) sf4[i] = f4[i];
    __syncthreads();

    const int warp = tid >> 5;
    const int lane = tid & 31;
    const int row  = blockIdx.x * WARPS_PER_BLOCK + warp;
    if (row >= NP) return;

    const float4* __restrict__ p4 =
        reinterpret_cast<const float4*>(proto + (size_t)row * ND);

    float acc = 0.0f;
#pragma unroll
    for (int it = 0; it < (ND / 4) / 32; it++) {   // 16 iterations
        const int idx = it * 32 + lane;
        float4 p = p4[idx];
        float4 f = sf4[idx];
        float d0 = p.x - f.x;
        float d1 = p.y - f.y;
        float d2 = p.z - f.z;
        float d3 = p.w - f.w;
        acc += d0 * d0 + d1 * d1 + d2 * d2 + d3 * d3;
    }

#pragma unroll
    for (int o = 16; o > 0; o >>= 1)
        acc += __shfl_xor_sync(0xFFFFFFFFu, acc, o);

    if (lane == 0) g_d[row] = acc;
}

// ---------------------------------------------------------------------------
// Kernel 2: single block. Pass 1: min(d) for stability. Pass 2: sum of
// exp(-(d - dmin)). Then probability = sum_k (log_one + d[label*K + k]),
// log_one = -dmin + log(sum).
// ---------------------------------------------------------------------------
__global__ __launch_bounds__(1024)
void reduce_kernel(const int* __restrict__ label_p, float* __restrict__ out) {
    __shared__ float sred[32];
    const int tid  = threadIdx.x;
    const int lane = tid & 31;
    const int warp = tid >> 5;

    // ---- pass 1: global min of d ----
    float mn = 3.402823466e38f;
    for (int i = tid; i < NP; i += 1024) mn = fminf(mn, g_d[i]);
#pragma unroll
    for (int o = 16; o > 0; o >>= 1)
        mn = fminf(mn, __shfl_xor_sync(0xFFFFFFFFu, mn, o));
    if (lane == 0) sred[warp] = mn;
    __syncthreads();
    if (warp == 0) {
        float v = sred[lane];
#pragma unroll
        for (int o = 16; o > 0; o >>= 1)
            v = fminf(v, __shfl_xor_sync(0xFFFFFFFFu, v, o));
        if (lane == 0) sred[0] = v;
    }
    __syncthreads();
    const float dmin = sred[0];
    __syncthreads();

    // ---- pass 2: sum exp(-(d - dmin)) ----
    float s = 0.0f;
    for (int i = tid; i < NP; i += 1024) s += expf(-(g_d[i] - dmin));
#pragma unroll
    for (int o = 16; o > 0; o >>= 1)
        s += __shfl_xor_sync(0xFFFFFFFFu, s, o);
    if (lane == 0) sred[warp] = s;
    __syncthreads();

    if (tid == 0) {
        float tot = 0.0f;
        for (int w = 0; w < 32; w++) tot += sred[w];
        const float log_one = -dmin + logf(tot);
        const int   label   = *label_p;
        float prob = 0.0f;
#pragma unroll
        for (int k = 0; k < NK; k++)
            prob += log_one + g_d[label * NK + k];
        out[0] = prob;
    }
}

// ---------------------------------------------------------------------------
// Harness entry. Inputs (metadata order): feature [2048 f32], label [1 i32],
// all_prototypes [10000*4*2048 f32]. Output: 1 f32.
// ---------------------------------------------------------------------------
extern "C" void kernel_launch(void* const* d_in, const int* in_sizes, int n_in,
                              void* d_out, int out_size) {
    const float* feat  = (const float*)d_in[0];
    const int*   label = (const int*)d_in[1];
    const float* proto = (const float*)d_in[2];
    float*       out   = (float*)d_out;

    dist_kernel<<<GRID_BLOCKS, BLOCK_THREADS>>>(proto, feat);
    reduce_kernel<<<1, 1024>>>(label, out);
}

// round 4
// speedup vs baseline: 1.0702x; 1.0702x over previous
#include <cuda_runtime.h>

#define NC 10000
#define NK 4
#define ND 2048
#define NP (NC * NK)                 // 40000 prototypes
#define RPB 32                       // rows (prototypes) per block = warps per block
#define BLOCK_THREADS (RPB * 32)     // 1024
#define GRID_BLOCKS (NP / RPB)       // 1250

// Scratch (device globals — no allocation allowed in kernel_launch)
__device__ float  g_d[NP];                 // squared distances (only label rows read later)
__device__ float2 g_part[GRID_BLOCKS];     // per-block (min_d, sum exp(min_d - d))

// ---------------------------------------------------------------------------
// Kernel 1: one warp per prototype row; block-level online logsumexp partial.
// ---------------------------------------------------------------------------
__global__ __launch_bounds__(BLOCK_THREADS)
void dist_kernel(const float* __restrict__ proto, const float* __restrict__ feat) {
    __shared__ float4 sf4[ND / 4];      // 8 KB feature cache
    __shared__ float  sd[RPB];          // per-warp row distances

    const int tid = threadIdx.x;
    const float4* __restrict__ f4 = reinterpret_cast<const float4*>(feat);
#pragma unroll
    for (int i = tid; i < ND / 4; i += BLOCK_THREADS) sf4[i] = f4[i];
    __syncthreads();

    const int warp = tid >> 5;
    const int lane = tid & 31;
    const int row  = blockIdx.x * RPB + warp;

    const float4* __restrict__ p4 =
        reinterpret_cast<const float4*>(proto + (size_t)row * ND);

    float acc = 0.0f;
#pragma unroll
    for (int it = 0; it < (ND / 4) / 32; it++) {   // 16 independent float4 loads
        const int idx = it * 32 + lane;
        float4 p = p4[idx];
        float4 f = sf4[idx];
        float d0 = p.x - f.x;
        float d1 = p.y - f.y;
        float d2 = p.z - f.z;
        float d3 = p.w - f.w;
        acc += d0 * d0 + d1 * d1 + d2 * d2 + d3 * d3;
    }

#pragma unroll
    for (int o = 16; o > 0; o >>= 1)
        acc += __shfl_xor_sync(0xFFFFFFFFu, acc, o);

    if (lane == 0) {
        g_d[row]  = acc;   // needed later only for the label rows (cheap to store all)
        sd[warp]  = acc;
    }
    __syncthreads();

    // warp 0: online logsumexp partial over this block's 32 row distances
    if (warp == 0) {
        float d = sd[lane];
        float m = d;
#pragma unroll
        for (int o = 16; o > 0; o >>= 1)
            m = fminf(m, __shfl_xor_sync(0xFFFFFFFFu, m, o));
        float e = expf(m - d);          // exp(-(d - m)), in (0, 1]
#pragma unroll
        for (int o = 16; o > 0; o >>= 1)
            e += __shfl_xor_sync(0xFFFFFFFFu, e, o);
        if (lane == 0) g_part[blockIdx.x] = make_float2(m, e);
    }
}

// ---------------------------------------------------------------------------
// Kernel 2: single block combines 1250 partials (10 KB, L2-resident).
//   m* = min_b m_b;  one = sum_b s_b * exp(m* - m_b)
//   prob = sum_k ( -m* + log(one) + d[label*K + k] )
// ---------------------------------------------------------------------------
__global__ __launch_bounds__(1024)
void combine_kernel(const int* __restrict__ label_p, float* __restrict__ out) {
    __shared__ float sred[32];
    __shared__ float s_min;

    const int tid  = threadIdx.x;
    const int lane = tid & 31;
    const int warp = tid >> 5;

    // load my partials (<= 2 per thread)
    float m0 = 3.402823466e38f, m1 = 3.402823466e38f;
    float2 p0 = make_float2(0.f, 0.f), p1 = make_float2(0.f, 0.f);
    if (tid < GRID_BLOCKS)        { p0 = g_part[tid];        m0 = p0.x; }
    if (tid + 1024 < GRID_BLOCKS) { p1 = g_part[tid + 1024]; m1 = p1.x; }

    // ---- global min of m_b ----
    float mn = fminf(m0, m1);
#pragma unroll
    for (int o = 16; o > 0; o >>= 1)
        mn = fminf(mn, __shfl_xor_sync(0xFFFFFFFFu, mn, o));
    if (lane == 0) sred[warp] = mn;
    __syncthreads();
    if (warp == 0) {
        float v = sred[lane];
#pragma unroll
        for (int o = 16; o > 0; o >>= 1)
            v = fminf(v, __shfl_xor_sync(0xFFFFFFFFu, v, o));
        if (lane == 0) s_min = v;
    }
    __syncthreads();
    const float mstar = s_min;

    // ---- combine sums: s_b * exp(mstar - m_b) ----
    float s = 0.0f;
    if (tid < GRID_BLOCKS)        s += p0.y * expf(mstar - p0.x);
    if (tid + 1024 < GRID_BLOCKS) s += p1.y * expf(mstar - p1.x);
#pragma unroll
    for (int o = 16; o > 0; o >>= 1)
        s += __shfl_xor_sync(0xFFFFFFFFu, s, o);
    if (lane == 0) sred[warp] = s;
    __syncthreads();

    if (tid == 0) {
        float tot = 0.0f;
#pragma unroll
        for (int w = 0; w < 32; w++) tot += sred[w];
        const float log_one = -mstar + logf(tot);
        const int   label   = *label_p;
        float prob = 0.0f;
#pragma unroll
        for (int k = 0; k < NK; k++)
            prob += log_one + g_d[label * NK + k];
        out[0] = prob;
    }
}

// ---------------------------------------------------------------------------
// Inputs (metadata order): feature [2048 f32], label [1 i32],
// all_prototypes [10000*4*2048 f32]. Output: 1 f32.
// ---------------------------------------------------------------------------
extern "C" void kernel_launch(void* const* d_in, const int* in_sizes, int n_in,
                              void* d_out, int out_size) {
    const float* feat  = (const float*)d_in[0];
    const int*   label = (const int*)d_in[1];
    const float* proto = (const float*)d_in[2];
    float*       out   = (float*)d_out;

    dist_kernel<<<GRID_BLOCKS, BLOCK_THREADS>>>(proto, feat);
    combine_kernel<<<1, 1024>>>(label, out);
}